// round 8
// baseline (speedup 1.0000x reference)
#include <cuda_runtime.h>

// Problem constants (fixed by reference: B=16, T=64, C=8, dyadic order 2)
#define NB     16
#define TT     64
#define CC     8
#define NC     63            // coarse increment grid (T-1)
#define NF     252           // fine grid N = (T-1)*4
#define NPAIRS 136           // a <= b pairs (K is symmetric)
#define NIT2   157           // 2-col skewed wavefront iterations per warp
#define BI     8             // iterations per progress block
#define NBLK   20            // ceil(157/8)

__device__ float g_K[NB * NB];
__device__ int   g_count = 0;

__global__ __launch_bounds__(128, 1)
void sig_fused_kernel(const float* __restrict__ paths, float* __restrict__ out) {
    // packP[jc*64 + u] = (c1, c2) for coarse row u, coef column jc:
    //   jc 0 -> identity, jc 1..63 -> coarse col jc-1, jc 64..66 -> identity
    __shared__ float2 packP[67 * 64];                      // 34304 B
    __shared__ __align__(16) float Gs[33][65];             // 8580 B (ring overlay later)
    __shared__ __align__(16) float Xa[TT][CC];             // 2 KB
    __shared__ __align__(16) float Xb[TT][CC];             // 2 KB
    __shared__ int prog[4];                                // producer progress counters
    __shared__ int s_last;

    const int tid = threadIdx.x;

    // ---- map block -> ordered pair (a <= b) ----
    int idx = blockIdx.x;
    int a = 0;
    while (idx >= NB - a) { idx -= NB - a; ++a; }
    const int b = a + idx;

    // ---- stage the two paths: X[i][c] = paths[batch][c][i] ----
    const float* pa = paths + a * (CC * TT);
    const float* pb = paths + b * (CC * TT);
    for (int e = tid; e < CC * TT; e += 128) {
        int c = e >> 6;
        int i = e & 63;
        Xa[i][c] = pa[e];
        Xb[i][c] = pb[e];
    }
    if (tid < 4) prog[tid] = 0;
    __syncthreads();

    // Gram strip: Gs[u - uBase][v] = exp(-||Xa_u - Xb_v||^2)
    auto fill_gram = [&](int uBase, int nRows) {
        const float4* xa4 = (const float4*)&Xa[0][0];
        const float4* xb4 = (const float4*)&Xb[0][0];
        for (int e = tid; e < nRows * 64; e += 128) {
            int ur = e >> 6, v = e & 63;
            int u  = uBase + ur;
            float4 a0 = xa4[2 * u], a1 = xa4[2 * u + 1];
            float4 b0 = xb4[2 * v], b1 = xb4[2 * v + 1];
            float d = 0.f, t;
            t = a0.x - b0.x; d = fmaf(t, t, d);
            t = a0.y - b0.y; d = fmaf(t, t, d);
            t = a0.z - b0.z; d = fmaf(t, t, d);
            t = a0.w - b0.w; d = fmaf(t, t, d);
            t = a1.x - b1.x; d = fmaf(t, t, d);
            t = a1.y - b1.y; d = fmaf(t, t, d);
            t = a1.z - b1.z; d = fmaf(t, t, d);
            t = a1.w - b1.w; d = fmaf(t, t, d);
            Gs[ur][v] = __expf(-d);
        }
    };

    // Build pack entries for coarse rows [uBase, uBase+32)
    auto build_pack = [&](int uBase) {
        for (int e = tid; e < 32 * 67; e += 128) {
            int uo = e & 31;
            int jc = e >> 5;           // 0..66
            float2 cc = make_float2(1.f, 1.f);
            if (jc >= 1 && jc <= 63) {
                int v = jc - 1;
                int r = uo;            // u=63 entry is garbage but never read (u clamped to 62)
                float A = (Gs[r + 1][v + 1] + Gs[r][v] - Gs[r + 1][v] - Gs[r][v + 1]) * (1.0f / 16.0f);
                float q = A * A * (1.0f / 12.0f);
                cc = make_float2(1.0f + 0.5f * A + q, 1.0f - q);
            }
            packP[jc * 64 + (uBase + uo)] = cc;
        }
    };

    fill_gram(0, 33);
    __syncthreads();
    build_pack(0);
    __syncthreads();
    fill_gram(32, 32);
    __syncthreads();
    build_pack(32);
    __syncthreads();

    // ---- 4-warp pipelined wavefront ----
    // Warp w owns fine rows 64w+1 .. 64w+64; lane l owns rows 64w+2l+1, 64w+2l+2.
    // At iter s, lane l computes cols j0=2(s-l)+1, j1=j0+1 (shared coarse col (s-l)>>1).
    // Boundary row 64w flows warp (w-1) -> warp w via rings[w-1][s] = (K[64w][j0],K[64w][j1])
    // written at producer iter s (lane 31). Consumer iter s reads entry s+31 (prefetch s+32).
    // Synchronization: monotone progress counters (spin+nanosleep), lost-event-free,
    // feed-forward chain -> deadlock-impossible; warps sit on distinct SMSPs -> no starvation.
    float2* rings = (float2*)&Gs[0][0];    // 3 * 157 * 8 = 3768 B <= 8580 B (Gs is dead now)

    const int wid = tid >> 5;
    const int l   = tid & 31;
    int u = 16 * wid + (l >> 1);
    if (u > 62) u = 62;                    // rows > 252 compute garbage, never consumed

    float2* ringUp = rings + (wid > 0 ? (wid - 1) * NIT2 : 0);
    float2* ringDn = rings + (wid < 3 ? wid * NIT2 : 0);
    volatile int* progUp = (wid > 0) ? &prog[wid - 1] : &prog[0];

    float p0 = 1.f, p1 = 1.f;              // K[row][j-1] for the 2 owned rows
    float topPrev = 1.f;                   // K[64w+2l][j-1]
    float vlo = 1.f, vhi = 1.f;            // bottom-row pair fed to lane l+1
    float result = 0.f;

    int i0 = ((-l) >> 1) + 1; if (i0 < 0) i0 = 0;
    float2 c  = packP[i0 * 64 + u];
    float2 rg = make_float2(1.f, 1.f);

    int s = 0;
    for (int m = 0; m < NBLK; ++m) {
        if (wid > 0) {
            int needS = BI * m + 40; if (needS > NIT2) needS = NIT2;  // prefetch horizon
            while (*progUp < needS) { __nanosleep(20); }
            __threadfence_block();
            if (m == 0) rg = ringUp[31];                              // boundary cols 1,2
        }
        int send = s + BI; if (send > NIT2) send = NIT2;
        for (; s < send; ++s) {
            float tc0 = __shfl_up_sync(0xffffffffu, vlo, 1);  // K[top][j0]
            float tc1 = __shfl_up_sync(0xffffffffu, vhi, 1);  // K[top][j1]
            if (l == 0) {
                tc0 = (wid == 0) ? 1.f : rg.x;
                tc1 = (wid == 0) ? 1.f : rg.y;
            }
            // prefetch next coef + next ring value (latency hidden by this iter)
            int in = ((s + 1 - l) >> 1) + 1;
            in = in < 0 ? 0 : (in > 66 ? 66 : in);
            float2 cn  = packP[in * 64 + u];
            float2 rgn = rg;
            if (wid > 0) {
                int ri = s + 32; if (ri > NIT2 - 1) ri = NIT2 - 1;
                rgn = ringUp[ri];
            }
            // column j0
            float h0 = fmaf(p0, c.x, -(topPrev * c.y));
            float h1 = fmaf(p1, c.x, -(p0 * c.y));
            float v0 = fmaf(tc0, c.x, h0);
            float v1 = fmaf(v0, c.x, h1);
            // column j1 (left neighbors are the fresh v's)
            float g0 = fmaf(v0, c.x, -(tc0 * c.y));
            float g1 = fmaf(v1, c.x, -(v0 * c.y));
            float q0 = fmaf(tc1, c.x, g0);
            float q1 = fmaf(q0, c.x, g1);

            topPrev = tc1;
            p0 = q0; p1 = q1;
            vlo = v1; vhi = q1;
            c = cn; rg = rgn;

            if (wid < 3 && l == 31) ringDn[s] = make_float2(v1, q1);  // boundary row 64(w+1)
            result = (s == 154) ? q1 : result;   // warp3 lane29: row 252, col 252
        }
        if (wid < 3 && l == 31) {
            __threadfence_block();               // ring stores visible before counter bump
            *((volatile int*)&prog[wid]) = send;
        }
    }

    if (tid == 3 * 32 + 29) {              // warp 3, lane 29
        g_K[a * NB + b] = result;
        g_K[b * NB + a] = result;          // symmetry
    }
    __syncthreads();

    // ---- last block to finish does the (16,2) reduction ----
    if (tid == 0) {
        __threadfence();
        int prev = atomicAdd(&g_count, 1);
        s_last = (prev == NPAIRS - 1) ? 1 : 0;
    }
    __syncthreads();
    if (s_last) {
        __threadfence();
        if (tid < NB) {
            float sm = 0.0f;
            #pragma unroll
            for (int bb = 0; bb < NB; ++bb) sm += __ldcg(&g_K[tid * NB + bb]);
            out[2 * tid]     = __ldcg(&g_K[tid * NB + tid]);
            out[2 * tid + 1] = sm * (1.0f / (float)NB);
        }
        if (tid == 0) g_count = 0;         // reset for next graph replay
    }
}

extern "C" void kernel_launch(void* const* d_in, const int* in_sizes, int n_in,
                              void* d_out, int out_size) {
    const float* paths = (const float*)d_in[0];
    sig_fused_kernel<<<NPAIRS, 128>>>(paths, (float*)d_out);
}

// round 10
// speedup vs baseline: 1.1091x; 1.1091x over previous
#include <cuda_runtime.h>

// Problem constants (fixed by reference: B=16, T=64, C=8, dyadic order 2)
#define NB     16
#define TT     64
#define CC     8
#define NC     63            // coarse increment grid (T-1)
#define NF     252           // fine grid N = (T-1)*4
#define NPAIRS 136           // a <= b pairs (K is symmetric)
#define NITP   160           // padded 2-col wavefront iterations (real: 157)
#define BI     8             // iterations per progress block
#define NBLK   20            // NITP / BI

__device__ float g_K[NB * NB];
__device__ int   g_count = 0;

__global__ __launch_bounds__(128, 1)
void sig_fused_kernel(const float* __restrict__ paths, float* __restrict__ out) {
    // packP[jc*64 + u] = (c1, c2) for coarse ROW u (lane-owned), coef column jc:
    //   jc 0 -> identity, jc 1..63 -> coarse col jc-1, jc 64 -> identity (tail)
    __shared__ float2 packP[65 * 64];                      // 33280 B
    __shared__ __align__(16) float Gs[33][65];             // 8580 B (ring overlay later)
    __shared__ __align__(16) float Xa[TT][CC];             // 2 KB
    __shared__ __align__(16) float Xb[TT][CC];             // 2 KB
    __shared__ int prog;                                   // warp0 progress counter
    __shared__ int s_last;

    const int tid = threadIdx.x;

    // ---- map block -> ordered pair (a <= b) ----
    int idx = blockIdx.x;
    int a = 0;
    while (idx >= NB - a) { idx -= NB - a; ++a; }
    const int b = a + idx;

    // ---- stage the two paths: X[i][c] = paths[batch][c][i] ----
    const float* pa = paths + a * (CC * TT);
    const float* pb = paths + b * (CC * TT);
    for (int e = tid; e < CC * TT; e += 128) {
        int c = e >> 6;
        int i = e & 63;
        Xa[i][c] = pa[e];
        Xb[i][c] = pb[e];
    }
    if (tid == 0) prog = 0;
    __syncthreads();

    // Gram strip: Gs[u - uBase][v] = exp(-||Xa_u - Xb_v||^2)
    auto fill_gram = [&](int uBase, int nRows) {
        const float4* xa4 = (const float4*)&Xa[0][0];
        const float4* xb4 = (const float4*)&Xb[0][0];
        for (int e = tid; e < nRows * 64; e += 128) {
            int ur = e >> 6, v = e & 63;
            int uu = uBase + ur;
            float4 a0 = xa4[2 * uu], a1 = xa4[2 * uu + 1];
            float4 b0 = xb4[2 * v],  b1 = xb4[2 * v + 1];
            float d = 0.f, t;
            t = a0.x - b0.x; d = fmaf(t, t, d);
            t = a0.y - b0.y; d = fmaf(t, t, d);
            t = a0.z - b0.z; d = fmaf(t, t, d);
            t = a0.w - b0.w; d = fmaf(t, t, d);
            t = a1.x - b1.x; d = fmaf(t, t, d);
            t = a1.y - b1.y; d = fmaf(t, t, d);
            t = a1.z - b1.z; d = fmaf(t, t, d);
            t = a1.w - b1.w; d = fmaf(t, t, d);
            Gs[ur][v] = __expf(-d);
        }
    };

    // Build pack entries for coarse rows [uBase, uBase+32)
    auto build_pack = [&](int uBase) {
        for (int e = tid; e < 32 * 65; e += 128) {
            int uo = e & 31;
            int jc = e >> 5;           // 0..64
            float2 cc = make_float2(1.f, 1.f);
            if (jc >= 1 && jc <= 63) {
                int v = jc - 1;
                int r = uo;
                if (uBase + uo == 63) r = 30;   // u=63 entry never read; keep finite
                float A = (Gs[r + 1][v + 1] + Gs[r][v] - Gs[r + 1][v] - Gs[r][v + 1]) * (1.0f / 16.0f);
                float q = A * A * (1.0f / 12.0f);
                cc = make_float2(1.0f + 0.5f * A + q, 1.0f - q);
            }
            packP[jc * 64 + (uBase + uo)] = cc;
        }
    };

    fill_gram(0, 33);
    __syncthreads();
    build_pack(0);
    __syncthreads();
    fill_gram(32, 32);
    __syncthreads();
    build_pack(32);
    __syncthreads();

    // ---- 2-warp pipelined wavefront ----
    // Warp w (0,1) owns fine rows 128w+1 .. 128w+128; lane l owns 4 rows
    // 128w+4l+1 .. 128w+4l+4 = exactly coarse row u = 32w+l -> ONE (c1,c2) per lane.
    // At iter s, lane l computes cols j0=2(s-l)+1, j1=j0+1.
    // Boundary row 128 flows warp0 -> warp1 via ring[s] = (K[128][j0], K[128][j1])
    // written by warp0 lane31 at its iter s; warp1 lane0 iter s reads ring[s+31].
    // Sync: monotone progress counter (plain spin), lost-event-free; warp0 never waits.
    float2* ring = (float2*)&Gs[0][0];     // 160 * 8 = 1280 B (Gs is dead now)

    const int wid = tid >> 5;
    const int l   = tid & 31;
    float result = 0.f;

    if (wid < 2) {
        int u = 32 * wid + l;
        if (u > 62) u = 62;                // warp1 lane31 = rows 253..256 (garbage, unread)
        volatile int* vprog = &prog;

        float p0 = 1.f, p1 = 1.f, p2 = 1.f, p3 = 1.f;   // K[row][j-1] for 4 owned rows
        float topPrev = 1.f;                            // K[top][j-1]
        float vlo = 1.f, vhi = 1.f;                     // bottom-row pair for lane l+1

        for (int m = 0; m < NBLK; ++m) {
            if (wid == 1) {
                int needS = BI * m + 40; if (needS > NITP) needS = NITP;
                while (*vprog < needS) { }
                __threadfence_block();
            }
            #pragma unroll
            for (int k = 0; k < BI; ++k) {
                const int s = m * BI + k;
                float tc0 = __shfl_up_sync(0xffffffffu, vlo, 1);  // K[top][j0]
                float tc1 = __shfl_up_sync(0xffffffffu, vhi, 1);  // K[top][j1]
                float2 rg = make_float2(1.f, 1.f);                // warp0 boundary = 1
                if (wid == 1) {
                    int ri = s + 31; if (ri > NITP - 1) ri = NITP - 1;
                    rg = ring[ri];                                // broadcast LDS
                }
                if (l == 0) { tc0 = rg.x; tc1 = rg.y; }

                int in = ((s - l) >> 1) + 1;                      // coarse coef column
                in = in < 0 ? 0 : (in > 64 ? 64 : in);
                float2 c = packP[in * 64 + u];

                // column j0: v_r = c1*(up + left) - c2*diag
                float t0 = fmaf(p0, c.x, -(topPrev * c.y));
                float t1 = fmaf(p1, c.x, -(p0 * c.y));
                float t2 = fmaf(p2, c.x, -(p1 * c.y));
                float t3 = fmaf(p3, c.x, -(p2 * c.y));
                float v0 = fmaf(tc0, c.x, t0);
                float v1 = fmaf(v0, c.x, t1);
                float v2 = fmaf(v1, c.x, t2);
                float v3 = fmaf(v2, c.x, t3);
                // column j1 (left neighbors are the fresh v's)
                float w0 = fmaf(v0, c.x, -(tc0 * c.y));
                float w1 = fmaf(v1, c.x, -(v0 * c.y));
                float w2 = fmaf(v2, c.x, -(v1 * c.y));
                float w3 = fmaf(v3, c.x, -(v2 * c.y));
                float q0 = fmaf(tc1, c.x, w0);
                float q1 = fmaf(q0, c.x, w1);
                float q2 = fmaf(q1, c.x, w2);
                float q3 = fmaf(q2, c.x, w3);

                topPrev = tc1;
                p0 = q0; p1 = q1; p2 = q2; p3 = q3;
                vlo = v3; vhi = q3;

                if (wid == 0 && l == 31) ring[s] = make_float2(v3, q3);  // row 128 pair
                if (s == 155) result = q3;   // warp1 lane30: row 252, col 252
            }
            if (wid == 0 && l == 31) {
                __threadfence_block();                   // ring visible before post
                *vprog = (m + 1) * BI;
            }
        }
    }

    if (tid == 32 + 30) {                  // warp 1, lane 30
        g_K[a * NB + b] = result;
        g_K[b * NB + a] = result;          // symmetry
    }
    __syncthreads();

    // ---- last block to finish does the (16,2) reduction ----
    if (tid == 0) {
        __threadfence();
        int prev = atomicAdd(&g_count, 1);
        s_last = (prev == NPAIRS - 1) ? 1 : 0;
    }
    __syncthreads();
    if (s_last) {
        __threadfence();
        if (tid < NB) {
            float sm = 0.0f;
            #pragma unroll
            for (int bb = 0; bb < NB; ++bb) sm += __ldcg(&g_K[tid * NB + bb]);
            out[2 * tid]     = __ldcg(&g_K[tid * NB + tid]);
            out[2 * tid + 1] = sm * (1.0f / (float)NB);
        }
        if (tid == 0) g_count = 0;         // reset for next graph replay
    }
}

extern "C" void kernel_launch(void* const* d_in, const int* in_sizes, int n_in,
                              void* d_out, int out_size) {
    const float* paths = (const float*)d_in[0];
    sig_fused_kernel<<<NPAIRS, 128>>>(paths, (float*)d_out);
}

// round 11
// speedup vs baseline: 1.1779x; 1.0621x over previous
#include <cuda_runtime.h>

// Problem constants (fixed by reference: B=16, T=64, C=8, dyadic order 2)
#define NB     16
#define TT     64
#define CC     8
#define NC     63            // coarse increment grid (T-1)
#define NF     252           // fine grid N = (T-1)*4
#define NPAIRS 136           // a <= b pairs (K is symmetric)
#define NIT4   94            // 4-col skewed wavefront iterations (63 real + 31 skew)

__device__ float g_K[NB * NB];
__device__ int   g_count = 0;

__global__ __launch_bounds__(128, 1)
void sig_fused_kernel(const float* __restrict__ paths, float* __restrict__ out) {
    // Packed per-lane coefficients: pack[l*65 + idx] = {c1A, c2A, c1B, c2B}
    //   idx 0      -> identity (1,1,1,1)  [pre-start]
    //   idx 1..63  -> coarse column idx-1
    //   idx 64     -> identity            [tail; garbage never reaches live lanes]
    __shared__ float4 pack[32 * 65];                  // 33280 B
    __shared__ float  Gs[33][65];                     // 8580 B Gram strip (padded)
    __shared__ __align__(16) float Xa[TT][CC];        // 2 KB
    __shared__ __align__(16) float Xb[TT][CC];        // 2 KB
    __shared__ int    s_last;

    const int tid = threadIdx.x;

    // ---- map block -> ordered pair (a <= b) ----
    int idx = blockIdx.x;
    int a = 0;
    while (idx >= NB - a) { idx -= NB - a; ++a; }
    const int b = a + idx;

    // ---- stage the two paths: X[i][c] = paths[batch][c][i] ----
    const float* pa = paths + a * (CC * TT);
    const float* pb = paths + b * (CC * TT);
    for (int e = tid; e < CC * TT; e += 128) {
        int c = e >> 6;
        int i = e & 63;
        Xa[i][c] = pa[e];
        Xb[i][c] = pb[e];
    }
    __syncthreads();

    // Gram strip: Gs[u - uBase][v] = exp(-||Xa_u - Xb_v||^2)
    auto fill_gram = [&](int uBase, int nRows) {
        const float4* xa4 = (const float4*)&Xa[0][0];
        const float4* xb4 = (const float4*)&Xb[0][0];
        for (int e = tid; e < nRows * 64; e += 128) {
            int ur = e >> 6, v = e & 63;
            int u  = uBase + ur;
            float4 a0 = xa4[2 * u], a1 = xa4[2 * u + 1];
            float4 b0 = xb4[2 * v], b1 = xb4[2 * v + 1];
            float d = 0.f, t;
            t = a0.x - b0.x; d = fmaf(t, t, d);
            t = a0.y - b0.y; d = fmaf(t, t, d);
            t = a0.z - b0.z; d = fmaf(t, t, d);
            t = a0.w - b0.w; d = fmaf(t, t, d);
            t = a1.x - b1.x; d = fmaf(t, t, d);
            t = a1.y - b1.y; d = fmaf(t, t, d);
            t = a1.z - b1.z; d = fmaf(t, t, d);
            t = a1.w - b1.w; d = fmaf(t, t, d);
            Gs[ur][v] = __expf(-d);
        }
    };

    // Pack builder for 16 lanes [lBase, lBase+16); Gs holds rows uBase..uBase+nRows-1
    auto build_pack = [&](int lBase, int uBase) {
        for (int e = tid; e < 16 * 65; e += 128) {
            int l  = lBase + e / 65;
            int jc = e - (e / 65) * 65;
            float4 c4 = make_float4(1.f, 1.f, 1.f, 1.f);
            if (jc >= 1 && jc <= 63) {
                int v  = jc - 1;
                int u0 = 2 * l;     if (u0 > NC - 1) u0 = NC - 1;
                int u1 = 2 * l + 1; if (u1 > NC - 1) u1 = NC - 1;
                int r0 = u0 - uBase, r1 = u1 - uBase;
                float A0 = (Gs[r0 + 1][v + 1] + Gs[r0][v] - Gs[r0 + 1][v] - Gs[r0][v + 1]) * (1.0f / 16.0f);
                float A1 = (Gs[r1 + 1][v + 1] + Gs[r1][v] - Gs[r1 + 1][v] - Gs[r1][v + 1]) * (1.0f / 16.0f);
                float q0 = A0 * A0 * (1.0f / 12.0f);
                float q1 = A1 * A1 * (1.0f / 12.0f);
                c4 = make_float4(1.0f + 0.5f * A0 + q0, 1.0f - q0,
                                 1.0f + 0.5f * A1 + q1, 1.0f - q1);
            }
            pack[l * 65 + jc] = c4;
        }
    };

    fill_gram(0, 33);
    __syncthreads();
    build_pack(0, 0);
    __syncthreads();
    fill_gram(32, 32);
    __syncthreads();
    build_pack(16, 32);
    __syncthreads();

    // ---- warp 0: barrier-free skewed wavefront, 4 fine columns per iteration ----
    // Lane l owns fine rows 8l+1 .. 8l+8 (coarse rows 2l, 2l+1).
    // At iter s (t = s-l), lane l processes cols 4t+1 .. 4t+4 = coarse column t
    // -> ONE float4 coef load per iteration, index = clamp(t+1, 0, 64).
    float result = 0.0f;
    if (tid < 32) {
        const int l = tid;
        const float4* packL = &pack[l * 65];

        float p0 = 1.f, p1 = 1.f, p2 = 1.f, p3 = 1.f;
        float p4 = 1.f, p5 = 1.f, p6 = 1.f, p7 = 1.f;   // K[rows][group-left col]
        float topPrev = 1.f;                            // K[8l][group-left col]
        float bt0 = 1.f, bt1 = 1.f, bt2 = 1.f, bt3 = 1.f; // bottom-row 4-col group

        #pragma unroll 2
        for (int s = 0; s < NIT4; ++s) {
            float tc0 = __shfl_up_sync(0xffffffffu, bt0, 1);  // K[8l][4t+1..4t+4]
            float tc1 = __shfl_up_sync(0xffffffffu, bt1, 1);
            float tc2 = __shfl_up_sync(0xffffffffu, bt2, 1);
            float tc3 = __shfl_up_sync(0xffffffffu, bt3, 1);
            if (l == 0) { tc0 = 1.f; tc1 = 1.f; tc2 = 1.f; tc3 = 1.f; }

            int ci = s - l + 1;
            ci = ci < 0 ? 0 : (ci > 64 ? 64 : ci);
            float4 c = packL[ci];

            // ---- column 0 of group ----
            float h0 = fmaf(p0, c.x, -(topPrev * c.y));
            float h1 = fmaf(p1, c.x, -(p0 * c.y));
            float h2 = fmaf(p2, c.x, -(p1 * c.y));
            float h3 = fmaf(p3, c.x, -(p2 * c.y));
            float h4 = fmaf(p4, c.z, -(p3 * c.w));
            float h5 = fmaf(p5, c.z, -(p4 * c.w));
            float h6 = fmaf(p6, c.z, -(p5 * c.w));
            float h7 = fmaf(p7, c.z, -(p6 * c.w));
            float v0 = fmaf(tc0, c.x, h0);
            float v1 = fmaf(v0, c.x, h1);
            float v2 = fmaf(v1, c.x, h2);
            float v3 = fmaf(v2, c.x, h3);
            float v4 = fmaf(v3, c.z, h4);
            float v5 = fmaf(v4, c.z, h5);
            float v6 = fmaf(v5, c.z, h6);
            float v7 = fmaf(v6, c.z, h7);
            // ---- column 1 ----
            float g0 = fmaf(v0, c.x, -(tc0 * c.y));
            float g1 = fmaf(v1, c.x, -(v0 * c.y));
            float g2 = fmaf(v2, c.x, -(v1 * c.y));
            float g3 = fmaf(v3, c.x, -(v2 * c.y));
            float g4 = fmaf(v4, c.z, -(v3 * c.w));
            float g5 = fmaf(v5, c.z, -(v4 * c.w));
            float g6 = fmaf(v6, c.z, -(v5 * c.w));
            float g7 = fmaf(v7, c.z, -(v6 * c.w));
            float w0 = fmaf(tc1, c.x, g0);
            float w1 = fmaf(w0, c.x, g1);
            float w2 = fmaf(w1, c.x, g2);
            float w3 = fmaf(w2, c.x, g3);
            float w4 = fmaf(w3, c.z, g4);
            float w5 = fmaf(w4, c.z, g5);
            float w6 = fmaf(w5, c.z, g6);
            float w7 = fmaf(w6, c.z, g7);
            // ---- column 2 ----
            float e0 = fmaf(w0, c.x, -(tc1 * c.y));
            float e1 = fmaf(w1, c.x, -(w0 * c.y));
            float e2 = fmaf(w2, c.x, -(w1 * c.y));
            float e3 = fmaf(w3, c.x, -(w2 * c.y));
            float e4 = fmaf(w4, c.z, -(w3 * c.w));
            float e5 = fmaf(w5, c.z, -(w4 * c.w));
            float e6 = fmaf(w6, c.z, -(w5 * c.w));
            float e7 = fmaf(w7, c.z, -(w6 * c.w));
            float x0 = fmaf(tc2, c.x, e0);
            float x1 = fmaf(x0, c.x, e1);
            float x2 = fmaf(x1, c.x, e2);
            float x3 = fmaf(x2, c.x, e3);
            float x4 = fmaf(x3, c.z, e4);
            float x5 = fmaf(x4, c.z, e5);
            float x6 = fmaf(x5, c.z, e6);
            float x7 = fmaf(x6, c.z, e7);
            // ---- column 3 ----
            float f0 = fmaf(x0, c.x, -(tc2 * c.y));
            float f1 = fmaf(x1, c.x, -(x0 * c.y));
            float f2 = fmaf(x2, c.x, -(x1 * c.y));
            float f3 = fmaf(x3, c.x, -(x2 * c.y));
            float f4 = fmaf(x4, c.z, -(x3 * c.w));
            float f5 = fmaf(x5, c.z, -(x4 * c.w));
            float f6 = fmaf(x6, c.z, -(x5 * c.w));
            float f7 = fmaf(x7, c.z, -(x6 * c.w));
            float y0 = fmaf(tc3, c.x, f0);
            float y1 = fmaf(y0, c.x, f1);
            float y2 = fmaf(y1, c.x, f2);
            float y3 = fmaf(y2, c.x, f3);
            float y4 = fmaf(y3, c.z, f4);
            float y5 = fmaf(y4, c.z, f5);
            float y6 = fmaf(y5, c.z, f6);
            float y7 = fmaf(y6, c.z, f7);

            topPrev = tc3;
            p0 = y0; p1 = y1; p2 = y2; p3 = y3;
            p4 = y4; p5 = y5; p6 = y6; p7 = y7;
            bt0 = v7; bt1 = w7; bt2 = x7; bt3 = y7;
        }
        result = p3;   // lane 31: fine row 252 at column 252 -> K[N][N]
    }

    if (tid == 31) {
        g_K[a * NB + b] = result;
        g_K[b * NB + a] = result;   // symmetry
    }
    __syncthreads();

    // ---- last block to finish does the (16,2) reduction ----
    if (tid == 0) {
        __threadfence();
        int prev = atomicAdd(&g_count, 1);
        s_last = (prev == NPAIRS - 1) ? 1 : 0;
    }
    __syncthreads();
    if (s_last) {
        __threadfence();
        if (tid < NB) {
            float sm = 0.0f;
            #pragma unroll
            for (int bb = 0; bb < NB; ++bb) sm += __ldcg(&g_K[tid * NB + bb]);
            out[2 * tid]     = __ldcg(&g_K[tid * NB + tid]);
            out[2 * tid + 1] = sm * (1.0f / (float)NB);
        }
        if (tid == 0) g_count = 0;   // reset for next graph replay
    }
}

extern "C" void kernel_launch(void* const* d_in, const int* in_sizes, int n_in,
                              void* d_out, int out_size) {
    const float* paths = (const float*)d_in[0];
    sig_fused_kernel<<<NPAIRS, 128>>>(paths, (float*)d_out);
}

// round 12
// speedup vs baseline: 1.2113x; 1.0284x over previous
#include <cuda_runtime.h>

// Problem constants (fixed by reference: B=16, T=64, C=8, dyadic order 2)
#define NB     16
#define TT     64
#define CC     8
#define NC     63            // coarse increment grid (T-1)
#define NF     252           // fine grid N = (T-1)*4
#define NPAIRS 136           // a <= b pairs (K is symmetric)
#define NITH   94            // 63 real column-pairs + 31 skew, per direction

__device__ float g_K[NB * NB];
__device__ int   g_count = 0;

__global__ __launch_bounds__(128, 1)
void sig_fused_kernel(const float* __restrict__ paths, float* __restrict__ out) {
    // pack[l*65 + idx] = {c1A, c2A, c1B, c2B} for lane l (coarse rows 2l, 2l+1):
    //   idx 0 -> identity, idx 1..63 -> coarse column idx-1, idx 64 -> identity
    __shared__ float4 pack[32 * 65];                  // 33280 B
    __shared__ __align__(16) float Gs[33 * 65];       // 8580 B; later overlay S/L arrays
    __shared__ __align__(16) float Xa[TT][CC];        // 2 KB
    __shared__ __align__(16) float Xb[TT][CC];        // 2 KB
    __shared__ float s_red[4];
    __shared__ float s_extra[2];                      // {lam0row, acc} from adjoint warp
    __shared__ int   s_last;

    const int tid = threadIdx.x;

    // ---- map block -> ordered pair (a <= b) ----
    int idx = blockIdx.x;
    int a = 0;
    while (idx >= NB - a) { idx -= NB - a; ++a; }
    const int b = a + idx;

    // ---- stage the two paths: X[i][c] = paths[batch][c][i] ----
    const float* pa = paths + a * (CC * TT);
    const float* pb = paths + b * (CC * TT);
    for (int e = tid; e < CC * TT; e += 128) {
        int c = e >> 6;
        int i = e & 63;
        Xa[i][c] = pa[e];
        Xb[i][c] = pb[e];
    }
    __syncthreads();

    // Gram strip: Gs[(u-uBase)*65 + v] = exp(-||Xa_u - Xb_v||^2)
    auto fill_gram = [&](int uBase, int nRows) {
        const float4* xa4 = (const float4*)&Xa[0][0];
        const float4* xb4 = (const float4*)&Xb[0][0];
        for (int e = tid; e < nRows * 64; e += 128) {
            int ur = e >> 6, v = e & 63;
            int u  = uBase + ur;
            float4 a0 = xa4[2 * u], a1 = xa4[2 * u + 1];
            float4 b0 = xb4[2 * v], b1 = xb4[2 * v + 1];
            float d = 0.f, t;
            t = a0.x - b0.x; d = fmaf(t, t, d);
            t = a0.y - b0.y; d = fmaf(t, t, d);
            t = a0.z - b0.z; d = fmaf(t, t, d);
            t = a0.w - b0.w; d = fmaf(t, t, d);
            t = a1.x - b1.x; d = fmaf(t, t, d);
            t = a1.y - b1.y; d = fmaf(t, t, d);
            t = a1.z - b1.z; d = fmaf(t, t, d);
            t = a1.w - b1.w; d = fmaf(t, t, d);
            Gs[ur * 65 + v] = __expf(-d);
        }
    };
    // Pack builder for 16 lanes [lBase, lBase+16); Gs holds rows uBase..uBase+nRows-1
    auto build_pack = [&](int lBase, int uBase) {
        for (int e = tid; e < 16 * 65; e += 128) {
            int l  = lBase + e / 65;
            int jc = e - (e / 65) * 65;
            float4 c4 = make_float4(1.f, 1.f, 1.f, 1.f);
            if (jc >= 1 && jc <= 63) {
                int v  = jc - 1;
                int u0 = 2 * l;     if (u0 > NC - 1) u0 = NC - 1;
                int u1 = 2 * l + 1; if (u1 > NC - 1) u1 = NC - 1;
                int r0 = u0 - uBase, r1 = u1 - uBase;
                float A0 = (Gs[(r0+1)*65 + v+1] + Gs[r0*65 + v] - Gs[(r0+1)*65 + v] - Gs[r0*65 + v+1]) * (1.0f/16.0f);
                float A1 = (Gs[(r1+1)*65 + v+1] + Gs[r1*65 + v] - Gs[(r1+1)*65 + v] - Gs[r1*65 + v+1]) * (1.0f/16.0f);
                float q0 = A0 * A0 * (1.0f / 12.0f);
                float q1 = A1 * A1 * (1.0f / 12.0f);
                c4 = make_float4(1.0f + 0.5f * A0 + q0, 1.0f - q0,
                                 1.0f + 0.5f * A1 + q1, 1.0f - q1);
            }
            pack[l * 65 + jc] = c4;
        }
    };

    fill_gram(0, 33);
    __syncthreads();
    build_pack(0, 0);
    __syncthreads();
    fill_gram(32, 32);
    __syncthreads();
    build_pack(16, 32);
    __syncthreads();

    // Overlays on dead Gram strip: S2f[j] = K[j+1][126], L2f[j] = lambda[j+1] at col 126
    float* S2f = Gs;          // 256 floats
    float* L2f = Gs + 256;    // 256 floats

    const int wid = tid >> 5;
    const int l   = tid & 31;

    if (wid == 0) {
        // ---- FORWARD warp: columns 1..126 (pairs t=0..62), lane l rows 8l+1..8l+8 ----
        const float4* packL = &pack[l * 65];
        float p0=1.f,p1=1.f,p2=1.f,p3=1.f,p4=1.f,p5=1.f,p6=1.f,p7=1.f;
        float topPrev = 1.f, vlo = 1.f, vhi = 1.f;

        #pragma unroll 2
        for (int s = 0; s < NITH; ++s) {
            float tc0 = __shfl_up_sync(0xffffffffu, vlo, 1);
            float tc1 = __shfl_up_sync(0xffffffffu, vhi, 1);
            if (l == 0) { tc0 = 1.f; tc1 = 1.f; }
            int t  = s - l;                       // column pair (cols 2t+1, 2t+2)
            int ci = (t >> 1) + 1;                // coarse column + 1
            ci = ci < 0 ? 0 : (ci > 64 ? 64 : ci);
            float4 c = packL[ci];

            float h0 = fmaf(p0, c.x, -(topPrev * c.y));
            float h1 = fmaf(p1, c.x, -(p0 * c.y));
            float h2 = fmaf(p2, c.x, -(p1 * c.y));
            float h3 = fmaf(p3, c.x, -(p2 * c.y));
            float h4 = fmaf(p4, c.z, -(p3 * c.w));
            float h5 = fmaf(p5, c.z, -(p4 * c.w));
            float h6 = fmaf(p6, c.z, -(p5 * c.w));
            float h7 = fmaf(p7, c.z, -(p6 * c.w));
            float v0 = fmaf(tc0, c.x, h0);
            float v1 = fmaf(v0, c.x, h1);
            float v2 = fmaf(v1, c.x, h2);
            float v3 = fmaf(v2, c.x, h3);
            float v4 = fmaf(v3, c.z, h4);
            float v5 = fmaf(v4, c.z, h5);
            float v6 = fmaf(v5, c.z, h6);
            float v7 = fmaf(v6, c.z, h7);
            float g0 = fmaf(v0, c.x, -(tc0 * c.y));
            float g1 = fmaf(v1, c.x, -(v0 * c.y));
            float g2 = fmaf(v2, c.x, -(v1 * c.y));
            float g3 = fmaf(v3, c.x, -(v2 * c.y));
            float g4 = fmaf(v4, c.z, -(v3 * c.w));
            float g5 = fmaf(v5, c.z, -(v4 * c.w));
            float g6 = fmaf(v6, c.z, -(v5 * c.w));
            float g7 = fmaf(v7, c.z, -(v6 * c.w));
            float w0 = fmaf(tc1, c.x, g0);
            float w1 = fmaf(w0, c.x, g1);
            float w2 = fmaf(w1, c.x, g2);
            float w3 = fmaf(w2, c.x, g3);
            float w4 = fmaf(w3, c.z, g4);
            float w5 = fmaf(w4, c.z, g5);
            float w6 = fmaf(w5, c.z, g6);
            float w7 = fmaf(w6, c.z, g7);

            topPrev = tc1;
            p0=w0; p1=w1; p2=w2; p3=w3; p4=w4; p5=w5; p6=w6; p7=w7;
            vlo = v7; vhi = w7;

            if (t == 62) {                        // state = column 126
                *(float4*)&S2f[l * 8]     = make_float4(p0, p1, p2, p3);
                *(float4*)&S2f[l * 8 + 4] = make_float4(p4, p5, p6, p7);
            }
        }
    } else if (wid == 1) {
        // ---- ADJOINT warp: consumes columns 252..127 (pairs k=0..62) ----
        // lambda rows 8l+1..8l+8 in L0..L7; gamma chain runs top->down (shfl_down).
        // Per column j: gam_i = lam_i + a_{i+1} gam_{i+1};  mu_i = a_i gam_i - b_{i+1} gam_{i+1}
        // Row 0: acc += lam0row + a_1*gam_1 ; lam0row <- -b_1*gam_1.
        const float4* packL = &pack[l * 65];
        const float2* packC = (const float2*)&pack[(l < 31 ? l + 1 : 31) * 65];
        float L0=0.f,L1=0.f,L2=0.f,L3=0.f,L4=0.f,L5=0.f,L6=0.f,L7=0.f;
        if (l == 31) L3 = 1.f;                    // lambda_252 = 1
        float lam0row = 0.f, acc = 0.f;
        float gpass_hi = 0.f, gpass_lo = 0.f;

        #pragma unroll 2
        for (int s = 0; s < NITH; ++s) {
            float gin0 = __shfl_down_sync(0xffffffffu, gpass_hi, 1);
            float gin1 = __shfl_down_sync(0xffffffffu, gpass_lo, 1);
            if (l == 31) { gin0 = 0.f; gin1 = 0.f; }
            int k  = s - (31 - l);                // pair k: cols (252-2k, 251-2k)
            int ci = ((125 - k) >> 1) + 1;        // coarse column + 1
            ci = ci < 0 ? 0 : (ci > 64 ? 64 : ci);
            float4 c  = packL[ci];                // aA=c.x bA=c.y aB=c.z bB=c.w
            float2 cc = packC[ci * 2];            // aC=cc.x bC=cc.y (coarse row 2l+2)

            // ---- column hi (252-2k) ----
            float g7 = fmaf(cc.x, gin0, L7);
            float g6 = fmaf(c.z, g7, L6);
            float g5 = fmaf(c.z, g6, L5);
            float g4 = fmaf(c.z, g5, L4);
            float g3 = fmaf(c.z, g4, L3);
            float g2 = fmaf(c.x, g3, L2);
            float g1 = fmaf(c.x, g2, L1);
            float g0 = fmaf(c.x, g1, L0);
            float m7 = fmaf(c.z, g7, -(cc.y * gin0));
            float m6 = fmaf(c.z, g6, -(c.w * g7));
            float m5 = fmaf(c.z, g5, -(c.w * g6));
            float m4 = fmaf(c.z, g4, -(c.w * g5));
            float m3 = fmaf(c.x, g3, -(c.w * g4));
            float m2 = fmaf(c.x, g2, -(c.y * g3));
            float m1 = fmaf(c.x, g1, -(c.y * g2));
            float m0 = fmaf(c.x, g0, -(c.y * g1));
            if (l == 0) { acc += fmaf(c.x, g0, lam0row); lam0row = -(c.y * g0); }
            // ---- column lo (251-2k) ----
            float h7 = fmaf(cc.x, gin1, m7);
            float h6 = fmaf(c.z, h7, m6);
            float h5 = fmaf(c.z, h6, m5);
            float h4 = fmaf(c.z, h5, m4);
            float h3 = fmaf(c.z, h4, m3);
            float h2 = fmaf(c.x, h3, m2);
            float h1 = fmaf(c.x, h2, m1);
            float h0 = fmaf(c.x, h1, m0);
            float n7 = fmaf(c.z, h7, -(cc.y * gin1));
            float n6 = fmaf(c.z, h6, -(c.w * h7));
            float n5 = fmaf(c.z, h5, -(c.w * h6));
            float n4 = fmaf(c.z, h4, -(c.w * h5));
            float n3 = fmaf(c.x, h3, -(c.w * h4));
            float n2 = fmaf(c.x, h2, -(c.y * h3));
            float n1 = fmaf(c.x, h1, -(c.y * h2));
            float n0 = fmaf(c.x, h0, -(c.y * h1));
            if (l == 0) { acc += fmaf(c.x, h0, lam0row); lam0row = -(c.y * h0); }

            L0=n0; L1=n1; L2=n2; L3=n3; L4=n4; L5=n5; L6=n6; L7=n7;
            gpass_hi = g0; gpass_lo = h0;

            if (k == 62) {                        // lambda for column 126
                *(float4*)&L2f[l * 8]     = make_float4(n0, n1, n2, n3);
                *(float4*)&L2f[l * 8 + 4] = make_float4(n4, n5, n6, n7);
                if (l == 0) { s_extra[0] = lam0row; s_extra[1] = acc; }
            }
        }
    }
    __syncthreads();

    // ---- combine: K[252][252] = sum_i L[i]*S[i] (i=1..252) + lam0row*1 + acc ----
    {
        float partial = 0.f;
        if (tid < 252)       partial  = S2f[tid] * L2f[tid];
        int j2 = tid + 128;
        if (j2 < 252)        partial += S2f[j2] * L2f[j2];
        #pragma unroll
        for (int o = 16; o; o >>= 1) partial += __shfl_xor_sync(0xffffffffu, partial, o);
        if ((tid & 31) == 0) s_red[tid >> 5] = partial;
    }
    __syncthreads();
    if (tid == 0) {
        float total = s_red[0] + s_red[1] + s_red[2] + s_red[3]
                    + s_extra[0] + s_extra[1];
        g_K[a * NB + b] = total;
        g_K[b * NB + a] = total;              // symmetry
    }
    __syncthreads();

    // ---- last block to finish does the (16,2) reduction ----
    if (tid == 0) {
        __threadfence();
        int prev = atomicAdd(&g_count, 1);
        s_last = (prev == NPAIRS - 1) ? 1 : 0;
    }
    __syncthreads();
    if (s_last) {
        __threadfence();
        if (tid < NB) {
            float sm = 0.0f;
            #pragma unroll
            for (int bb = 0; bb < NB; ++bb) sm += __ldcg(&g_K[tid * NB + bb]);
            out[2 * tid]     = __ldcg(&g_K[tid * NB + tid]);
            out[2 * tid + 1] = sm * (1.0f / (float)NB);
        }
        if (tid == 0) g_count = 0;            // reset for next graph replay
    }
}

extern "C" void kernel_launch(void* const* d_in, const int* in_sizes, int n_in,
                              void* d_out, int out_size) {
    const float* paths = (const float*)d_in[0];
    sig_fused_kernel<<<NPAIRS, 128>>>(paths, (float*)d_out);
}